// round 13
// baseline (speedup 1.0000x reference)
#include <cuda_runtime.h>
#include <cuda_fp16.h>
#include <cstdint>
#include <cstddef>

// Problem constants
#define HOPS 3
#define VV   50000
#define DD   128
#define BB   16
#define LC   256
#define MC   8
#define LK   512
#define MK   8
#define NPAIR (HOPS * BB)          // 48

// Attention tiling
#define TQ 64          // q rows per attn block (4 warps x 16-row strips)
#define TK 64          // kf rows per chunk
#define KS 2           // k-split factor
#define CHUNKS (LK / TK / KS)      // 4 chunks per attn block
#define KF_PITCH 136   // halves; 272B row stride (16B-odd -> conflict-free ldsm)

// Fused grid layout: per pair, 192 embed blocks (64 cf + 128 kf) then 8 attn
#define EMB_PER_PAIR 192
#define BLK_PER_PAIR 200
#define GRID_BLKS (NPAIR * BLK_PER_PAIR)   // 9600

// ---------------- device scratch (plain fp16) ----------------
__device__ __half g_cf[(size_t)HOPS * BB * LC * DD];
__device__ __half g_kf[(size_t)HOPS * BB * LK * DD];
__device__ float  g_part[(size_t)HOPS * KS * LC * BB * DD];  // unscaled partial AV
__device__ float  g_psum[(size_t)HOPS * KS * LC * BB];       // partial row sums
__device__ unsigned g_ready[NPAIR];                          // embed pair counters (0-init)

// ---------------- warp-MMA helpers (portable PTX) --------
__device__ __forceinline__ uint32_t smem_u32(const void* p) {
    uint32_t a;
    asm("{ .reg .u64 t; cvta.to.shared.u64 t, %1; cvt.u32.u64 %0, t; }"
        : "=r"(a) : "l"(p));
    return a;
}
__device__ __forceinline__ void ldsm_x4(uint32_t a[4], uint32_t addr) {
    asm volatile("ldmatrix.sync.aligned.m8n8.x4.shared.b16 {%0,%1,%2,%3}, [%4];"
                 : "=r"(a[0]), "=r"(a[1]), "=r"(a[2]), "=r"(a[3]) : "r"(addr));
}
__device__ __forceinline__ void ldsm_x4_t(uint32_t a[4], uint32_t addr) {
    asm volatile("ldmatrix.sync.aligned.m8n8.x4.trans.shared.b16 {%0,%1,%2,%3}, [%4];"
                 : "=r"(a[0]), "=r"(a[1]), "=r"(a[2]), "=r"(a[3]) : "r"(addr));
}
__device__ __forceinline__ void mma16816(float d[4], const uint32_t a[4],
                                         const uint32_t b0, const uint32_t b1) {
    asm volatile("mma.sync.aligned.m16n8k16.row.col.f32.f16.f16.f32 "
                 "{%0,%1,%2,%3}, {%4,%5,%6,%7}, {%8,%9}, {%0,%1,%2,%3};"
                 : "+f"(d[0]), "+f"(d[1]), "+f"(d[2]), "+f"(d[3])
                 : "r"(a[0]), "r"(a[1]), "r"(a[2]), "r"(a[3]),
                   "r"(b0), "r"(b1));
}
__device__ __forceinline__ void cp16(uint32_t dst, const void* src) {
    asm volatile("cp.async.cg.shared.global [%0], [%1], 16;"
                 :: "r"(dst), "l"(src) : "memory");
}
#define CP_COMMIT() asm volatile("cp.async.commit_group;" ::: "memory")
#define CP_WAIT0()  asm volatile("cp.async.wait_group 0;" ::: "memory")

__device__ __forceinline__ uint32_t h2u(float a, float b) {
    __half2 h = __floats2half2_rn(a, b);
    return *reinterpret_cast<uint32_t*>(&h);
}

// ---------------------------------------------------------------------------
// Fused kernel: grid = 9600 blocks x 128 threads.
// Per pair p (= hop*16 + b), blocks [200p, 200p+192) embed (4 rows each,
// 1 row/warp, MLP-8 — identical shape to the measured-best split embed),
// then blocks [200p+192, 200p+200) run the R12 attention (x = a&3, ksplit = a>>2)
// after spinning on g_ready[p] == 192.
// Deadlock-free: 444 co-resident slots (launch_bounds 128,3) > 384 attn blocks,
// and embed blocks never wait.
// ---------------------------------------------------------------------------
extern __shared__ __half smem_h[];

__global__ __launch_bounds__(128, 3)
void fused_kernel(const int* __restrict__ conv, const int* __restrict__ kb,
                  const float* __restrict__ Ctab, const float* __restrict__ Ktab) {
    const int bid  = blockIdx.x;
    const int p    = bid / BLK_PER_PAIR;
    const int rr   = bid - p * BLK_PER_PAIR;
    const int hop  = p >> 4;
    const int b    = p & 15;
    const int tid  = threadIdx.x;
    const int lane = tid & 31;
    const int w    = tid >> 5;

    // ================= embed blocks =================
    if (rr < EMB_PER_PAIR) {
        const int* idx;
        const float* tab;
        __half* dst;
        if (rr < 64) {                       // cf rows
            const int l = rr * 4 + w;
            idx = conv + (b * LC + l) * MC;
            tab = Ctab + (size_t)hop * VV * DD;
            dst = g_cf + ((size_t)p * LC + l) * DD;
        } else {                             // kf rows
            const int k = (rr - 64) * 4 + w;
            idx = kb + (b * LK + k) * MK;
            tab = Ktab + (size_t)hop * VV * DD;
            dst = g_kf + ((size_t)p * LK + k) * DD;
        }
        float4 s = make_float4(0.f, 0.f, 0.f, 0.f);
        #pragma unroll
        for (int m = 0; m < 8; m++) {
            const float4 v = ((const float4*)(tab + (size_t)idx[m] * DD))[lane];
            s.x += v.x; s.y += v.y; s.z += v.z; s.w += v.w;
        }
        ((__half2*)(dst + 4 * lane))[0] = __floats2half2_rn(s.x, s.y);
        ((__half2*)(dst + 4 * lane))[1] = __floats2half2_rn(s.z, s.w);
        __syncthreads();
        __threadfence();                     // release stores
        if (tid == 0) atomicAdd(&g_ready[p], 1u);
        return;
    }

    // ================= attn blocks =================
    const int a      = rr - EMB_PER_PAIR;    // 0..7
    const int xblk   = a & 3;
    const int ksplit = a >> 2;
    const int pair   = p;
    const int lbase  = xblk * TQ;

    if (tid == 0) {
        while (((volatile unsigned*)g_ready)[pair] < (unsigned)EMB_PER_PAIR)
            __nanosleep(128);
    }
    __syncthreads();
    __threadfence();                         // acquire embed stores

    const int g  = lane >> 2;
    const int t4 = lane & 3;

    const uint32_t sb = smem_u32(smem_h);
    const uint32_t BUFSZ = TK * KF_PITCH * 2;   // 17408 bytes per plane

    // ---- stage cf into plane 2 (plain stores), issue chunk0 cp.async ----
    {
        const uint4* sh = (const uint4*)(g_cf + ((size_t)pair * LC + lbase) * DD);
        __half* cfp = smem_h + 2 * TK * KF_PITCH;
        for (int i = tid; i < TQ * (DD / 8); i += 128) {
            const int r  = i >> 4;
            const int c8 = i & 15;
            *(uint4*)&cfp[r * KF_PITCH + c8 * 8] = sh[r * (DD / 8) + c8];
        }
        const int ch0 = ksplit * CHUNKS;
        const uint4* kh = (const uint4*)(g_kf + ((size_t)pair * LK + ch0 * TK) * DD);
        for (int i = tid; i < TK * (DD / 8); i += 128) {
            const int r  = i >> 4;
            const int c8 = i & 15;
            cp16(sb + (uint32_t)(r * KF_PITCH + c8 * 8) * 2u, kh + r * (DD / 8) + c8);
        }
        CP_COMMIT();
    }
    __syncthreads();                       // cf visible

    // ---- preload cf A-fragments from plane 2 ----
    uint32_t a_cf[8][4];
    {
        const int sub = lane >> 3;
        const int r8a = lane & 7;
        const int arow = w * 16 + r8a + ((sub & 1) << 3);
        const int acol0 = (sub & 2) << 2;
        const uint32_t cb = sb + 2 * BUFSZ;
        #pragma unroll
        for (int ks = 0; ks < 8; ks++) {
            const uint32_t off = (uint32_t)(arow * KF_PITCH + 16 * ks + acol0) * 2u;
            ldsm_x4(a_cf[ks], cb + off);
        }
    }
    CP_WAIT0();
    __syncthreads();                       // chunk0 ready; A-preload done

    // x4 lane addressing components
    const int r8   = lane & 7;
    const int gq   = lane >> 3;
    const uint32_t sc_row_off = (uint32_t)(((gq >> 1) << 3) + r8);
    const uint32_t sc_col_off = (uint32_t)((gq & 1) << 3);
    const uint32_t av_row_off = (uint32_t)(((gq & 1) << 3) + r8);
    const uint32_t av_col_off = (uint32_t)((gq >> 1) << 3);

    float out[16][4];
    #pragma unroll
    for (int i = 0; i < 16; i++)
        #pragma unroll
        for (int q = 0; q < 4; q++) out[i][q] = 0.f;
    float sum_r = 0.f, sum_r8 = 0.f;

    for (int c = 0; c < CHUNKS; c++) {
        if (c < CHUNKS - 1) {
            const int chn = ksplit * CHUNKS + c + 1;
            const uint32_t db = sb + (uint32_t)((c + 1) & 1) * BUFSZ;
            const uint4* kh = (const uint4*)(g_kf + ((size_t)pair * LK + chn * TK) * DD);
            for (int i = tid; i < TK * (DD / 8); i += 128) {
                const int r  = i >> 4;
                const int c8 = i & 15;
                cp16(db + (uint32_t)(r * KF_PITCH + c8 * 8) * 2u, kh + r * (DD / 8) + c8);
            }
            CP_COMMIT();
        }

        const uint32_t kf_b = sb + (uint32_t)(c & 1) * BUFSZ;

        // ---- scores + exp; 4 independent acc chains (32 kf rows / pass) ----
        uint32_t pa[4][4];
        #pragma unroll
        for (int pp = 0; pp < 2; pp++) {
            float acc[4][4];
            #pragma unroll
            for (int j = 0; j < 4; j++)
                #pragma unroll
                for (int q = 0; q < 4; q++) acc[j][q] = 0.f;
            const uint32_t rbA = (uint32_t)(pp * 32) + sc_row_off;
            const uint32_t rbB = rbA + 16;
            #pragma unroll
            for (int ks = 0; ks < 8; ks++) {
                uint32_t bA[4], bB[4];
                const uint32_t ko = (uint32_t)(16 * ks) + sc_col_off;
                ldsm_x4(bA, kf_b + (rbA * KF_PITCH + ko) * 2u);
                ldsm_x4(bB, kf_b + (rbB * KF_PITCH + ko) * 2u);
                mma16816(acc[0], a_cf[ks], bA[0], bA[1]);
                mma16816(acc[1], a_cf[ks], bA[2], bA[3]);
                mma16816(acc[2], a_cf[ks], bB[0], bB[1]);
                mma16816(acc[3], a_cf[ks], bB[2], bB[3]);
            }
            #pragma unroll
            for (int j = 0; j < 4; j++) {
                const int nb = 4 * pp + j;
                const float e0 = __expf(acc[j][0]);
                const float e1 = __expf(acc[j][1]);
                const float e2 = __expf(acc[j][2]);
                const float e3 = __expf(acc[j][3]);
                sum_r  += e0 + e1;
                sum_r8 += e2 + e3;
                // D-layout == AV A-layout identity
                pa[nb >> 1][((nb & 1) << 1) + 0] = h2u(e0, e1);
                pa[nb >> 1][((nb & 1) << 1) + 1] = h2u(e2, e3);
            }
        }

        // ---- AV: A = P (regs), B = kf via x4 trans (two dn per load) ----
        #pragma unroll
        for (int dnp = 0; dnp < 8; dnp++) {
            const uint32_t cb = (uint32_t)(dnp * 16) + av_col_off;
            #pragma unroll
            for (int ks = 0; ks < 4; ks++) {
                uint32_t b_h[4];
                const uint32_t off =
                    (((uint32_t)(16 * ks) + av_row_off) * KF_PITCH + cb) * 2u;
                ldsm_x4_t(b_h, kf_b + off);
                mma16816(out[2 * dnp],     pa[ks], b_h[0], b_h[1]);
                mma16816(out[2 * dnp + 1], pa[ks], b_h[2], b_h[3]);
            }
        }

        if (c < CHUNKS - 1) {
            CP_WAIT0();
            __syncthreads();               // next chunk ready; buffer swap safe
        }
    }

    // ---- finalize: quad-reduce row sums, store UNSCALED partials + sums ----
    #pragma unroll
    for (int off = 1; off <= 2; off <<= 1) {
        sum_r  += __shfl_xor_sync(0xffffffffu, sum_r,  off);
        sum_r8 += __shfl_xor_sync(0xffffffffu, sum_r8, off);
    }
    const int z = hop * KS + ksplit;
    const int l0 = lbase + w * 16 + g;
    float* slab = g_part + (size_t)z * LC * BB * DD;
    float* op0 = slab + ((size_t)l0 * BB + b) * DD;
    float* op8 = slab + ((size_t)(l0 + 8) * BB + b) * DD;
    if (t4 == 0) {
        g_psum[(size_t)z * LC * BB + (size_t)l0 * BB + b]       = sum_r;
        g_psum[(size_t)z * LC * BB + (size_t)(l0 + 8) * BB + b] = sum_r8;
    }
    #pragma unroll
    for (int dn = 0; dn < 16; dn++) {
        const int col = dn * 8 + 2 * t4;
        *(float2*)&op0[col] = make_float2(out[dn][0], out[dn][1]);
        *(float2*)&op8[col] = make_float2(out[dn][2], out[dn][3]);
    }
}

// ---------------------------------------------------------------------------
// Kernel 2: combine k-split partials, sum hops -> out [LC, B, D];
// also resets g_ready for the next graph replay.
// ---------------------------------------------------------------------------
__global__ void reduce_kernel(float* __restrict__ out) {
    const int i = blockIdx.x * blockDim.x + threadIdx.x;     // float4 index
    if (blockIdx.x == 0 && threadIdx.x < NPAIR) g_ready[threadIdx.x] = 0u;
    const int rowIdx = i >> 5;                               // (l*BB+b)
    const size_t N4 = (size_t)LC * BB * (DD / 4);
    float4 r = make_float4(0.f, 0.f, 0.f, 0.f);
    #pragma unroll
    for (int hop = 0; hop < HOPS; hop++) {
        const float s = g_psum[(size_t)(hop * KS) * LC * BB + rowIdx] +
                        g_psum[(size_t)(hop * KS + 1) * LC * BB + rowIdx];
        const float inv = 1.f / s;
        const float4 a = ((const float4*)g_part)[(size_t)(hop * KS) * N4 + i];
        const float4 c = ((const float4*)g_part)[(size_t)(hop * KS + 1) * N4 + i];
        r.x += (a.x + c.x) * inv;
        r.y += (a.y + c.y) * inv;
        r.z += (a.z + c.z) * inv;
        r.w += (a.w + c.w) * inv;
    }
    ((float4*)out)[i] = r;
}

// ---------------------------------------------------------------------------
extern "C" void kernel_launch(void* const* d_in, const int* in_sizes, int n_in,
                              void* d_out, int out_size) {
    const int*   conv = (const int*)d_in[0];
    const int*   kb   = (const int*)d_in[1];
    const float* Ctab = (const float*)d_in[2];
    const float* Ktab = (const float*)d_in[3];
    float* out = (float*)d_out;

    const int smem_bytes = 3 * TK * KF_PITCH * 2;        // 52224
    cudaFuncSetAttribute(fused_kernel,
                         cudaFuncAttributeMaxDynamicSharedMemorySize, smem_bytes);

    fused_kernel<<<GRID_BLKS, 128, smem_bytes>>>(conv, kb, Ctab, Ktab);
    const int n4 = LC * BB * DD / 4;                     // 131072
    reduce_kernel<<<n4 / 256, 256>>>(out);
}

// round 14
// speedup vs baseline: 1.4215x; 1.4215x over previous
#include <cuda_runtime.h>
#include <cuda_fp16.h>
#include <cstdint>
#include <cstddef>

// Problem constants
#define HOPS 3
#define VV   50000
#define DD   128
#define BB   16
#define LC   256
#define MC   8
#define LK   512
#define MK   8

// Attention tiling
#define TQ 64          // q rows per block (4 warps x 16-row strips)
#define TK 64          // kf rows per chunk
#define KS 2           // k-split factor
#define CHUNKS (LK / TK / KS)   // 4 chunks per block
#define KF_PITCH 136   // halves; 272B row stride (16B-odd -> conflict-free ldsm)

// ---------------- device scratch (plain fp16) ----------------
__device__ __half g_cf[(size_t)HOPS * BB * LC * DD];
__device__ __half g_kf[(size_t)HOPS * BB * LK * DD];
__device__ float  g_part[(size_t)HOPS * KS * LC * BB * DD];  // unscaled partial AV
__device__ float  g_psum[(size_t)HOPS * KS * LC * BB];       // partial row sums

// ---------------- warp-MMA helpers (portable PTX) --------
__device__ __forceinline__ uint32_t smem_u32(const void* p) {
    uint32_t a;
    asm("{ .reg .u64 t; cvta.to.shared.u64 t, %1; cvt.u32.u64 %0, t; }"
        : "=r"(a) : "l"(p));
    return a;
}
__device__ __forceinline__ void ldsm_x4(uint32_t a[4], uint32_t addr) {
    asm volatile("ldmatrix.sync.aligned.m8n8.x4.shared.b16 {%0,%1,%2,%3}, [%4];"
                 : "=r"(a[0]), "=r"(a[1]), "=r"(a[2]), "=r"(a[3]) : "r"(addr));
}
__device__ __forceinline__ void ldsm_x4_t(uint32_t a[4], uint32_t addr) {
    asm volatile("ldmatrix.sync.aligned.m8n8.x4.trans.shared.b16 {%0,%1,%2,%3}, [%4];"
                 : "=r"(a[0]), "=r"(a[1]), "=r"(a[2]), "=r"(a[3]) : "r"(addr));
}
__device__ __forceinline__ void mma16816(float d[4], const uint32_t a[4],
                                         const uint32_t b0, const uint32_t b1) {
    asm volatile("mma.sync.aligned.m16n8k16.row.col.f32.f16.f16.f32 "
                 "{%0,%1,%2,%3}, {%4,%5,%6,%7}, {%8,%9}, {%0,%1,%2,%3};"
                 : "+f"(d[0]), "+f"(d[1]), "+f"(d[2]), "+f"(d[3])
                 : "r"(a[0]), "r"(a[1]), "r"(a[2]), "r"(a[3]),
                   "r"(b0), "r"(b1));
}
__device__ __forceinline__ void cp16(uint32_t dst, const void* src) {
    asm volatile("cp.async.cg.shared.global [%0], [%1], 16;"
                 :: "r"(dst), "l"(src) : "memory");
}
#define CP_COMMIT() asm volatile("cp.async.commit_group;" ::: "memory")
#define CP_WAIT0()  asm volatile("cp.async.wait_group 0;" ::: "memory")

__device__ __forceinline__ uint32_t h2u(float a, float b) {
    __half2 h = __floats2half2_rn(a, b);
    return *reinterpret_cast<uint32_t*>(&h);
}

// ---------------------------------------------------------------------------
// Kernel 1: per-hop embedding-bag -> plain fp16. 1 row/warp, 4 rows/block.
// grid = 3072 blocks per hop (identical inner shape to the measured-best embed).
// ---------------------------------------------------------------------------
__global__ void embed_kernel(int hop,
                             const int* __restrict__ conv,
                             const int* __restrict__ kb,
                             const float* __restrict__ Ctab,
                             const float* __restrict__ Ktab) {
    const int lane = threadIdx.x & 31;
    const int row  = blockIdx.x * 4 + (threadIdx.x >> 5);   // 0..12287 within hop
    const int NCh  = BB * LC;                               // 4096

    const int* idx;
    const float* tab;
    __half* dst;
    if (row < NCh) {
        idx = conv + row * MC;
        tab = Ctab + (size_t)hop * VV * DD;
        dst = g_cf + ((size_t)hop * NCh + row) * DD;
    } else {
        const int r2 = row - NCh;
        idx = kb + r2 * MK;
        tab = Ktab + (size_t)hop * VV * DD;
        dst = g_kf + ((size_t)hop * BB * LK + r2) * DD;
    }
    float4 s = make_float4(0.f, 0.f, 0.f, 0.f);
    #pragma unroll
    for (int m = 0; m < 8; m++) {
        const float4 v = ((const float4*)(tab + (size_t)idx[m] * DD))[lane];
        s.x += v.x; s.y += v.y; s.z += v.z; s.w += v.w;
    }
    ((__half2*)(dst + 4 * lane))[0] = __floats2half2_rn(s.x, s.y);
    ((__half2*)(dst + 4 * lane))[1] = __floats2half2_rn(s.z, s.w);
}

// ---------------------------------------------------------------------------
// Kernel 2: per-hop warp-MMA flash attention (R12 math, hop as param).
// grid = (LC/TQ, BB, KS) = (4,16,2) = 128 blocks per hop, 128 thr, 3 blocks/SM.
// ---------------------------------------------------------------------------
extern __shared__ __half smem_h[];

__global__ __launch_bounds__(128, 3)
void attn_kernel(int hop) {
    const int tid  = threadIdx.x;
    const int lane = tid & 31;
    const int w    = tid >> 5;
    const int g    = lane >> 2;
    const int t4   = lane & 3;
    const int lbase  = blockIdx.x * TQ;
    const int b      = blockIdx.y;
    const int ksplit = blockIdx.z;
    const int pair   = hop * BB + b;

    const uint32_t sb = smem_u32(smem_h);
    const uint32_t BUFSZ = TK * KF_PITCH * 2;   // 17408 bytes per plane

    // ---- stage cf into plane 2 (plain stores), issue chunk0 cp.async ----
    {
        const uint4* sh = (const uint4*)(g_cf + ((size_t)pair * LC + lbase) * DD);
        __half* cfp = smem_h + 2 * TK * KF_PITCH;
        for (int i = tid; i < TQ * (DD / 8); i += 128) {
            const int r  = i >> 4;
            const int c8 = i & 15;
            *(uint4*)&cfp[r * KF_PITCH + c8 * 8] = sh[r * (DD / 8) + c8];
        }
        const int ch0 = ksplit * CHUNKS;
        const uint4* kh = (const uint4*)(g_kf + ((size_t)pair * LK + ch0 * TK) * DD);
        for (int i = tid; i < TK * (DD / 8); i += 128) {
            const int r  = i >> 4;
            const int c8 = i & 15;
            cp16(sb + (uint32_t)(r * KF_PITCH + c8 * 8) * 2u, kh + r * (DD / 8) + c8);
        }
        CP_COMMIT();
    }
    __syncthreads();                       // cf visible

    // ---- preload cf A-fragments from plane 2 ----
    uint32_t a_cf[8][4];
    {
        const int sub = lane >> 3;
        const int r8a = lane & 7;
        const int arow = w * 16 + r8a + ((sub & 1) << 3);
        const int acol0 = (sub & 2) << 2;
        const uint32_t cb = sb + 2 * BUFSZ;
        #pragma unroll
        for (int ks = 0; ks < 8; ks++) {
            const uint32_t off = (uint32_t)(arow * KF_PITCH + 16 * ks + acol0) * 2u;
            ldsm_x4(a_cf[ks], cb + off);
        }
    }
    CP_WAIT0();
    __syncthreads();                       // chunk0 ready; A-preload done

    // x4 lane addressing components
    const int r8   = lane & 7;
    const int gq   = lane >> 3;
    const uint32_t sc_row_off = (uint32_t)(((gq >> 1) << 3) + r8);
    const uint32_t sc_col_off = (uint32_t)((gq & 1) << 3);
    const uint32_t av_row_off = (uint32_t)(((gq & 1) << 3) + r8);
    const uint32_t av_col_off = (uint32_t)((gq >> 1) << 3);

    float out[16][4];
    #pragma unroll
    for (int i = 0; i < 16; i++)
        #pragma unroll
        for (int q = 0; q < 4; q++) out[i][q] = 0.f;
    float sum_r = 0.f, sum_r8 = 0.f;

    for (int c = 0; c < CHUNKS; c++) {
        if (c < CHUNKS - 1) {
            const int chn = ksplit * CHUNKS + c + 1;
            const uint32_t db = sb + (uint32_t)((c + 1) & 1) * BUFSZ;
            const uint4* kh = (const uint4*)(g_kf + ((size_t)pair * LK + chn * TK) * DD);
            for (int i = tid; i < TK * (DD / 8); i += 128) {
                const int r  = i >> 4;
                const int c8 = i & 15;
                cp16(db + (uint32_t)(r * KF_PITCH + c8 * 8) * 2u, kh + r * (DD / 8) + c8);
            }
            CP_COMMIT();
        }

        const uint32_t kf_b = sb + (uint32_t)(c & 1) * BUFSZ;

        // ---- scores + exp; 4 independent acc chains (32 kf rows / pass) ----
        uint32_t pa[4][4];
        #pragma unroll
        for (int p = 0; p < 2; p++) {
            float acc[4][4];
            #pragma unroll
            for (int j = 0; j < 4; j++)
                #pragma unroll
                for (int q = 0; q < 4; q++) acc[j][q] = 0.f;
            const uint32_t rbA = (uint32_t)(p * 32) + sc_row_off;
            const uint32_t rbB = rbA + 16;
            #pragma unroll
            for (int ks = 0; ks < 8; ks++) {
                uint32_t bA[4], bB[4];
                const uint32_t ko = (uint32_t)(16 * ks) + sc_col_off;
                ldsm_x4(bA, kf_b + (rbA * KF_PITCH + ko) * 2u);
                ldsm_x4(bB, kf_b + (rbB * KF_PITCH + ko) * 2u);
                mma16816(acc[0], a_cf[ks], bA[0], bA[1]);
                mma16816(acc[1], a_cf[ks], bA[2], bA[3]);
                mma16816(acc[2], a_cf[ks], bB[0], bB[1]);
                mma16816(acc[3], a_cf[ks], bB[2], bB[3]);
            }
            #pragma unroll
            for (int j = 0; j < 4; j++) {
                const int nb = 4 * p + j;
                const float e0 = __expf(acc[j][0]);
                const float e1 = __expf(acc[j][1]);
                const float e2 = __expf(acc[j][2]);
                const float e3 = __expf(acc[j][3]);
                sum_r  += e0 + e1;
                sum_r8 += e2 + e3;
                // D-layout == AV A-layout identity
                pa[nb >> 1][((nb & 1) << 1) + 0] = h2u(e0, e1);
                pa[nb >> 1][((nb & 1) << 1) + 1] = h2u(e2, e3);
            }
        }

        // ---- AV: A = P (regs), B = kf via x4 trans (two dn per load) ----
        #pragma unroll
        for (int dnp = 0; dnp < 8; dnp++) {
            const uint32_t cb = (uint32_t)(dnp * 16) + av_col_off;
            #pragma unroll
            for (int ks = 0; ks < 4; ks++) {
                uint32_t b_h[4];
                const uint32_t off =
                    (((uint32_t)(16 * ks) + av_row_off) * KF_PITCH + cb) * 2u;
                ldsm_x4_t(b_h, kf_b + off);
                mma16816(out[2 * dnp],     pa[ks], b_h[0], b_h[1]);
                mma16816(out[2 * dnp + 1], pa[ks], b_h[2], b_h[3]);
            }
        }

        if (c < CHUNKS - 1) {
            CP_WAIT0();
            __syncthreads();               // next chunk ready; buffer swap safe
        }
    }

    // ---- finalize: quad-reduce row sums, store UNSCALED partials + sums ----
    #pragma unroll
    for (int off = 1; off <= 2; off <<= 1) {
        sum_r  += __shfl_xor_sync(0xffffffffu, sum_r,  off);
        sum_r8 += __shfl_xor_sync(0xffffffffu, sum_r8, off);
    }
    const int z = hop * KS + ksplit;
    const int l0 = lbase + w * 16 + g;
    float* slab = g_part + (size_t)z * LC * BB * DD;
    float* op0 = slab + ((size_t)l0 * BB + b) * DD;
    float* op8 = slab + ((size_t)(l0 + 8) * BB + b) * DD;
    if (t4 == 0) {
        g_psum[(size_t)z * LC * BB + (size_t)l0 * BB + b]       = sum_r;
        g_psum[(size_t)z * LC * BB + (size_t)(l0 + 8) * BB + b] = sum_r8;
    }
    #pragma unroll
    for (int dn = 0; dn < 16; dn++) {
        const int col = dn * 8 + 2 * t4;
        *(float2*)&op0[col] = make_float2(out[dn][0], out[dn][1]);
        *(float2*)&op8[col] = make_float2(out[dn][2], out[dn][3]);
    }
}

// ---------------------------------------------------------------------------
// Kernel 3: combine k-split partials and sum hops -> out [LC, B, D]
// ---------------------------------------------------------------------------
__global__ void reduce_kernel(float* __restrict__ out) {
    const int i = blockIdx.x * blockDim.x + threadIdx.x;     // float4 index
    const int rowIdx = i >> 5;                               // (l*BB+b)
    const size_t N4 = (size_t)LC * BB * (DD / 4);
    float4 r = make_float4(0.f, 0.f, 0.f, 0.f);
    #pragma unroll
    for (int hop = 0; hop < HOPS; hop++) {
        const float s = g_psum[(size_t)(hop * KS) * LC * BB + rowIdx] +
                        g_psum[(size_t)(hop * KS + 1) * LC * BB + rowIdx];
        const float inv = 1.f / s;
        const float4 a = ((const float4*)g_part)[(size_t)(hop * KS) * N4 + i];
        const float4 c = ((const float4*)g_part)[(size_t)(hop * KS + 1) * N4 + i];
        r.x += (a.x + c.x) * inv;
        r.y += (a.y + c.y) * inv;
        r.z += (a.z + c.z) * inv;
        r.w += (a.w + c.w) * inv;
    }
    ((float4*)out)[i] = r;
}

// ---------------------------------------------------------------------------
// Host: fork-join pipeline. Embed hops on the main (captured) stream; each
// hop's attention launched on a second stream gated by an event, overlapping
// attn(h) with embed(h+1). Streams/events created once on the first
// (uncaptured correctness) call; all graph-time ops are capturable
// (kernel launches, event record, stream wait). No device allocation.
// ---------------------------------------------------------------------------
extern "C" void kernel_launch(void* const* d_in, const int* in_sizes, int n_in,
                              void* d_out, int out_size) {
    const int*   conv = (const int*)d_in[0];
    const int*   kb   = (const int*)d_in[1];
    const float* Ctab = (const float*)d_in[2];
    const float* Ktab = (const float*)d_in[3];
    float* out = (float*)d_out;

    static cudaStream_t s2 = nullptr;
    static cudaEvent_t evE[HOPS];
    static cudaEvent_t evJoin;
    if (s2 == nullptr) {
        cudaStreamCreateWithFlags(&s2, cudaStreamNonBlocking);
        for (int h = 0; h < HOPS; h++)
            cudaEventCreateWithFlags(&evE[h], cudaEventDisableTiming);
        cudaEventCreateWithFlags(&evJoin, cudaEventDisableTiming);
    }

    const int smem_bytes = 3 * TK * KF_PITCH * 2;        // 52224
    cudaFuncSetAttribute(attn_kernel,
                         cudaFuncAttributeMaxDynamicSharedMemorySize, smem_bytes);

    const int emb_blocks = BB * (LC + LK) / 4;           // 3072 per hop
    for (int h = 0; h < HOPS; h++) {
        embed_kernel<<<emb_blocks, 128>>>(h, conv, kb, Ctab, Ktab);
        cudaEventRecord(evE[h], 0);
        cudaStreamWaitEvent(s2, evE[h], 0);
        attn_kernel<<<dim3(LC / TQ, BB, KS), 128, smem_bytes, s2>>>(h);
    }
    cudaEventRecord(evJoin, s2);
    cudaStreamWaitEvent(0, evJoin, 0);

    const int n4 = LC * BB * DD / 4;                     // 131072
    reduce_kernel<<<n4 / 256, 256>>>(out);
}

// round 15
// speedup vs baseline: 1.4788x; 1.0403x over previous
#include <cuda_runtime.h>
#include <cuda_fp16.h>
#include <cstdint>
#include <cstddef>

// Problem constants
#define HOPS 3
#define VV   50000
#define DD   128
#define BB   16
#define LC   256
#define MC   8
#define LK   512
#define MK   8

// Attention tiling
#define TQ 64          // q rows per block (4 warps x 16-row strips)
#define TK 64          // kf rows per chunk
#define KS 4           // k-split factor (2 chunks per block)
#define CHUNKS (LK / TK / KS)   // 2 chunks per block
#define KF_PITCH 136   // halves; 272B row stride (16B-odd -> conflict-free ldsm)

// ---------------- device scratch (plain fp16) ----------------
__device__ __half g_cf[(size_t)HOPS * BB * LC * DD];
__device__ __half g_kf[(size_t)HOPS * BB * LK * DD];
__device__ float  g_part[(size_t)HOPS * KS * LC * BB * DD];  // unscaled partial AV
__device__ float  g_psum[(size_t)HOPS * KS * LC * BB];       // partial row sums

// ---------------- warp-MMA helpers (portable PTX) --------
__device__ __forceinline__ uint32_t smem_u32(const void* p) {
    uint32_t a;
    asm("{ .reg .u64 t; cvta.to.shared.u64 t, %1; cvt.u32.u64 %0, t; }"
        : "=r"(a) : "l"(p));
    return a;
}
__device__ __forceinline__ void ldsm_x4(uint32_t a[4], uint32_t addr) {
    asm volatile("ldmatrix.sync.aligned.m8n8.x4.shared.b16 {%0,%1,%2,%3}, [%4];"
                 : "=r"(a[0]), "=r"(a[1]), "=r"(a[2]), "=r"(a[3]) : "r"(addr));
}
__device__ __forceinline__ void ldsm_x4_t(uint32_t a[4], uint32_t addr) {
    asm volatile("ldmatrix.sync.aligned.m8n8.x4.trans.shared.b16 {%0,%1,%2,%3}, [%4];"
                 : "=r"(a[0]), "=r"(a[1]), "=r"(a[2]), "=r"(a[3]) : "r"(addr));
}
__device__ __forceinline__ void mma16816(float d[4], const uint32_t a[4],
                                         const uint32_t b0, const uint32_t b1) {
    asm volatile("mma.sync.aligned.m16n8k16.row.col.f32.f16.f16.f32 "
                 "{%0,%1,%2,%3}, {%4,%5,%6,%7}, {%8,%9}, {%0,%1,%2,%3};"
                 : "+f"(d[0]), "+f"(d[1]), "+f"(d[2]), "+f"(d[3])
                 : "r"(a[0]), "r"(a[1]), "r"(a[2]), "r"(a[3]),
                   "r"(b0), "r"(b1));
}
__device__ __forceinline__ void cp16(uint32_t dst, const void* src) {
    asm volatile("cp.async.cg.shared.global [%0], [%1], 16;"
                 :: "r"(dst), "l"(src) : "memory");
}
#define CP_COMMIT() asm volatile("cp.async.commit_group;" ::: "memory")
#define CP_WAIT0()  asm volatile("cp.async.wait_group 0;" ::: "memory")

__device__ __forceinline__ uint32_t h2u(float a, float b) {
    __half2 h = __floats2half2_rn(a, b);
    return *reinterpret_cast<uint32_t*>(&h);
}

// ---------------------------------------------------------------------------
// Kernel 1: per-hop embedding-bag -> plain fp16. 1 row/warp, 4 rows/block.
// grid = 3072 blocks per hop (measured-best embed shape).
// ---------------------------------------------------------------------------
__global__ void embed_kernel(int hop,
                             const int* __restrict__ conv,
                             const int* __restrict__ kb,
                             const float* __restrict__ Ctab,
                             const float* __restrict__ Ktab) {
    const int lane = threadIdx.x & 31;
    const int row  = blockIdx.x * 4 + (threadIdx.x >> 5);   // 0..12287 within hop
    const int NCh  = BB * LC;                               // 4096

    const int* idx;
    const float* tab;
    __half* dst;
    if (row < NCh) {
        idx = conv + row * MC;
        tab = Ctab + (size_t)hop * VV * DD;
        dst = g_cf + ((size_t)hop * NCh + row) * DD;
    } else {
        const int r2 = row - NCh;
        idx = kb + r2 * MK;
        tab = Ktab + (size_t)hop * VV * DD;
        dst = g_kf + ((size_t)hop * BB * LK + r2) * DD;
    }
    float4 s = make_float4(0.f, 0.f, 0.f, 0.f);
    #pragma unroll
    for (int m = 0; m < 8; m++) {
        const float4 v = ((const float4*)(tab + (size_t)idx[m] * DD))[lane];
        s.x += v.x; s.y += v.y; s.z += v.z; s.w += v.w;
    }
    ((__half2*)(dst + 4 * lane))[0] = __floats2half2_rn(s.x, s.y);
    ((__half2*)(dst + 4 * lane))[1] = __floats2half2_rn(s.z, s.w);
}

// ---------------------------------------------------------------------------
// Kernel 2: per-hop warp-MMA flash attention, KS=4 (2 chunks per block).
// grid = (LC/TQ, BB, KS) = (4,16,4) = 256 blocks per hop, 128 thr, 3 blocks/SM.
// ---------------------------------------------------------------------------
extern __shared__ __half smem_h[];

__global__ __launch_bounds__(128, 3)
void attn_kernel(int hop) {
    const int tid  = threadIdx.x;
    const int lane = tid & 31;
    const int w    = tid >> 5;
    const int g    = lane >> 2;
    const int t4   = lane & 3;
    const int lbase  = blockIdx.x * TQ;
    const int b      = blockIdx.y;
    const int ksplit = blockIdx.z;
    const int pair   = hop * BB + b;

    const uint32_t sb = smem_u32(smem_h);
    const uint32_t BUFSZ = TK * KF_PITCH * 2;   // 17408 bytes per plane

    // ---- stage cf into plane 2 (plain stores), issue chunk0 cp.async ----
    {
        const uint4* sh = (const uint4*)(g_cf + ((size_t)pair * LC + lbase) * DD);
        __half* cfp = smem_h + 2 * TK * KF_PITCH;
        for (int i = tid; i < TQ * (DD / 8); i += 128) {
            const int r  = i >> 4;
            const int c8 = i & 15;
            *(uint4*)&cfp[r * KF_PITCH + c8 * 8] = sh[r * (DD / 8) + c8];
        }
        const int ch0 = ksplit * CHUNKS;
        const uint4* kh = (const uint4*)(g_kf + ((size_t)pair * LK + ch0 * TK) * DD);
        for (int i = tid; i < TK * (DD / 8); i += 128) {
            const int r  = i >> 4;
            const int c8 = i & 15;
            cp16(sb + (uint32_t)(r * KF_PITCH + c8 * 8) * 2u, kh + r * (DD / 8) + c8);
        }
        CP_COMMIT();
    }
    __syncthreads();                       // cf visible

    // ---- preload cf A-fragments from plane 2 ----
    uint32_t a_cf[8][4];
    {
        const int sub = lane >> 3;
        const int r8a = lane & 7;
        const int arow = w * 16 + r8a + ((sub & 1) << 3);
        const int acol0 = (sub & 2) << 2;
        const uint32_t cb = sb + 2 * BUFSZ;
        #pragma unroll
        for (int ks = 0; ks < 8; ks++) {
            const uint32_t off = (uint32_t)(arow * KF_PITCH + 16 * ks + acol0) * 2u;
            ldsm_x4(a_cf[ks], cb + off);
        }
    }
    CP_WAIT0();
    __syncthreads();                       // chunk0 ready; A-preload done

    // x4 lane addressing components
    const int r8   = lane & 7;
    const int gq   = lane >> 3;
    const uint32_t sc_row_off = (uint32_t)(((gq >> 1) << 3) + r8);
    const uint32_t sc_col_off = (uint32_t)((gq & 1) << 3);
    const uint32_t av_row_off = (uint32_t)(((gq & 1) << 3) + r8);
    const uint32_t av_col_off = (uint32_t)((gq >> 1) << 3);

    float out[16][4];
    #pragma unroll
    for (int i = 0; i < 16; i++)
        #pragma unroll
        for (int q = 0; q < 4; q++) out[i][q] = 0.f;
    float sum_r = 0.f, sum_r8 = 0.f;

    for (int c = 0; c < CHUNKS; c++) {
        if (c < CHUNKS - 1) {
            const int chn = ksplit * CHUNKS + c + 1;
            const uint32_t db = sb + (uint32_t)((c + 1) & 1) * BUFSZ;
            const uint4* kh = (const uint4*)(g_kf + ((size_t)pair * LK + chn * TK) * DD);
            for (int i = tid; i < TK * (DD / 8); i += 128) {
                const int r  = i >> 4;
                const int c8 = i & 15;
                cp16(db + (uint32_t)(r * KF_PITCH + c8 * 8) * 2u, kh + r * (DD / 8) + c8);
            }
            CP_COMMIT();
        }

        const uint32_t kf_b = sb + (uint32_t)(c & 1) * BUFSZ;

        // ---- scores + exp; 4 independent acc chains (32 kf rows / pass) ----
        uint32_t pa[4][4];
        #pragma unroll
        for (int p = 0; p < 2; p++) {
            float acc[4][4];
            #pragma unroll
            for (int j = 0; j < 4; j++)
                #pragma unroll
                for (int q = 0; q < 4; q++) acc[j][q] = 0.f;
            const uint32_t rbA = (uint32_t)(p * 32) + sc_row_off;
            const uint32_t rbB = rbA + 16;
            #pragma unroll
            for (int ks = 0; ks < 8; ks++) {
                uint32_t bA[4], bB[4];
                const uint32_t ko = (uint32_t)(16 * ks) + sc_col_off;
                ldsm_x4(bA, kf_b + (rbA * KF_PITCH + ko) * 2u);
                ldsm_x4(bB, kf_b + (rbB * KF_PITCH + ko) * 2u);
                mma16816(acc[0], a_cf[ks], bA[0], bA[1]);
                mma16816(acc[1], a_cf[ks], bA[2], bA[3]);
                mma16816(acc[2], a_cf[ks], bB[0], bB[1]);
                mma16816(acc[3], a_cf[ks], bB[2], bB[3]);
            }
            #pragma unroll
            for (int j = 0; j < 4; j++) {
                const int nb = 4 * p + j;
                const float e0 = __expf(acc[j][0]);
                const float e1 = __expf(acc[j][1]);
                const float e2 = __expf(acc[j][2]);
                const float e3 = __expf(acc[j][3]);
                sum_r  += e0 + e1;
                sum_r8 += e2 + e3;
                // D-layout == AV A-layout identity
                pa[nb >> 1][((nb & 1) << 1) + 0] = h2u(e0, e1);
                pa[nb >> 1][((nb & 1) << 1) + 1] = h2u(e2, e3);
            }
        }

        // ---- AV: A = P (regs), B = kf via x4 trans (two dn per load) ----
        #pragma unroll
        for (int dnp = 0; dnp < 8; dnp++) {
            const uint32_t cb = (uint32_t)(dnp * 16) + av_col_off;
            #pragma unroll
            for (int ks = 0; ks < 4; ks++) {
                uint32_t b_h[4];
                const uint32_t off =
                    (((uint32_t)(16 * ks) + av_row_off) * KF_PITCH + cb) * 2u;
                ldsm_x4_t(b_h, kf_b + off);
                mma16816(out[2 * dnp],     pa[ks], b_h[0], b_h[1]);
                mma16816(out[2 * dnp + 1], pa[ks], b_h[2], b_h[3]);
            }
        }

        if (c < CHUNKS - 1) {
            CP_WAIT0();
            __syncthreads();               // next chunk ready; buffer swap safe
        }
    }

    // ---- finalize: quad-reduce row sums, store UNSCALED partials + sums ----
    #pragma unroll
    for (int off = 1; off <= 2; off <<= 1) {
        sum_r  += __shfl_xor_sync(0xffffffffu, sum_r,  off);
        sum_r8 += __shfl_xor_sync(0xffffffffu, sum_r8, off);
    }
    const int z = hop * KS + ksplit;
    const int l0 = lbase + w * 16 + g;
    float* slab = g_part + (size_t)z * LC * BB * DD;
    float* op0 = slab + ((size_t)l0 * BB + b) * DD;
    float* op8 = slab + ((size_t)(l0 + 8) * BB + b) * DD;
    if (t4 == 0) {
        g_psum[(size_t)z * LC * BB + (size_t)l0 * BB + b]       = sum_r;
        g_psum[(size_t)z * LC * BB + (size_t)(l0 + 8) * BB + b] = sum_r8;
    }
    #pragma unroll
    for (int dn = 0; dn < 16; dn++) {
        const int col = dn * 8 + 2 * t4;
        *(float2*)&op0[col] = make_float2(out[dn][0], out[dn][1]);
        *(float2*)&op8[col] = make_float2(out[dn][2], out[dn][3]);
    }
}

// ---------------------------------------------------------------------------
// Kernel 3: combine KS partials per hop and sum hops -> out [LC, B, D]
// ---------------------------------------------------------------------------
__global__ void reduce_kernel(float* __restrict__ out) {
    const int i = blockIdx.x * blockDim.x + threadIdx.x;     // float4 index
    const int rowIdx = i >> 5;                               // (l*BB+b)
    const size_t N4 = (size_t)LC * BB * (DD / 4);
    float4 r = make_float4(0.f, 0.f, 0.f, 0.f);
    #pragma unroll
    for (int hop = 0; hop < HOPS; hop++) {
        float s = 0.f;
        float4 acc = make_float4(0.f, 0.f, 0.f, 0.f);
        #pragma unroll
        for (int ks = 0; ks < KS; ks++) {
            const int z = hop * KS + ks;
            s += g_psum[(size_t)z * LC * BB + rowIdx];
            const float4 a = ((const float4*)g_part)[(size_t)z * N4 + i];
            acc.x += a.x; acc.y += a.y; acc.z += a.z; acc.w += a.w;
        }
        const float inv = 1.f / s;
        r.x += acc.x * inv;
        r.y += acc.y * inv;
        r.z += acc.z * inv;
        r.w += acc.w * inv;
    }
    ((float4*)out)[i] = r;
}

// ---------------------------------------------------------------------------
// Host: fork-join pipeline with ONE STREAM PER HOP for the attention
// (R14's failure was serializing the three attns on a single stream).
// attn(h) overlaps embed(h+1) and attn(h+1) start. All ops capturable;
// statics created on the first (uncaptured correctness) call.
// ---------------------------------------------------------------------------
extern "C" void kernel_launch(void* const* d_in, const int* in_sizes, int n_in,
                              void* d_out, int out_size) {
    const int*   conv = (const int*)d_in[0];
    const int*   kb   = (const int*)d_in[1];
    const float* Ctab = (const float*)d_in[2];
    const float* Ktab = (const float*)d_in[3];
    float* out = (float*)d_out;

    static cudaStream_t sA[HOPS] = {nullptr, nullptr, nullptr};
    static cudaEvent_t evE[HOPS];
    static cudaEvent_t evJ[HOPS];
    if (sA[0] == nullptr) {
        for (int h = 0; h < HOPS; h++) {
            cudaStreamCreateWithFlags(&sA[h], cudaStreamNonBlocking);
            cudaEventCreateWithFlags(&evE[h], cudaEventDisableTiming);
            cudaEventCreateWithFlags(&evJ[h], cudaEventDisableTiming);
        }
    }

    const int smem_bytes = 3 * TK * KF_PITCH * 2;        // 52224
    cudaFuncSetAttribute(attn_kernel,
                         cudaFuncAttributeMaxDynamicSharedMemorySize, smem_bytes);

    const int emb_blocks = BB * (LC + LK) / 4;           // 3072 per hop
    for (int h = 0; h < HOPS; h++) {
        embed_kernel<<<emb_blocks, 128>>>(h, conv, kb, Ctab, Ktab);
        cudaEventRecord(evE[h], 0);
        cudaStreamWaitEvent(sA[h], evE[h], 0);
        attn_kernel<<<dim3(LC / TQ, BB, KS), 128, smem_bytes, sA[h]>>>(h);
        cudaEventRecord(evJ[h], sA[h]);
    }
    for (int h = 0; h < HOPS; h++)
        cudaStreamWaitEvent(0, evJ[h], 0);

    const int n4 = LC * BB * DD / 4;                     // 131072
    reduce_kernel<<<n4 / 256, 256>>>(out);
}

// round 16
// speedup vs baseline: 1.7849x; 1.2070x over previous
#include <cuda_runtime.h>
#include <cuda_fp16.h>
#include <cstdint>
#include <cstddef>

// Problem constants
#define HOPS 3
#define VV   50000
#define DD   128
#define BB   16
#define LC   256
#define MC   8
#define LK   512
#define MK   8

// Attention tiling
#define TQ 64          // q rows per block (4 warps x 16-row strips)
#define TK 64          // kf rows per chunk
#define KS 2           // k-split factor
#define CHUNKS (LK / TK / KS)   // 4 chunks per block
#define KF_PITCH 136   // halves; 272B row stride (16B-odd -> conflict-free ldsm)

// ---------------- device scratch ----------------
__device__ __half g_cf[(size_t)HOPS * BB * LC * DD];
__device__ __half g_kf[(size_t)HOPS * BB * LK * DD];
__device__ __half g_part[(size_t)HOPS * KS * LC * BB * DD]; // fp16 partial AV
__device__ float  g_psum[(size_t)HOPS * KS * LC * BB];      // partial row sums

// ---------------- warp-MMA helpers (portable PTX) --------
__device__ __forceinline__ uint32_t smem_u32(const void* p) {
    uint32_t a;
    asm("{ .reg .u64 t; cvta.to.shared.u64 t, %1; cvt.u32.u64 %0, t; }"
        : "=r"(a) : "l"(p));
    return a;
}
__device__ __forceinline__ void ldsm_x4(uint32_t a[4], uint32_t addr) {
    asm volatile("ldmatrix.sync.aligned.m8n8.x4.shared.b16 {%0,%1,%2,%3}, [%4];"
                 : "=r"(a[0]), "=r"(a[1]), "=r"(a[2]), "=r"(a[3]) : "r"(addr));
}
__device__ __forceinline__ void ldsm_x4_t(uint32_t a[4], uint32_t addr) {
    asm volatile("ldmatrix.sync.aligned.m8n8.x4.trans.shared.b16 {%0,%1,%2,%3}, [%4];"
                 : "=r"(a[0]), "=r"(a[1]), "=r"(a[2]), "=r"(a[3]) : "r"(addr));
}
__device__ __forceinline__ void mma16816(float d[4], const uint32_t a[4],
                                         const uint32_t b0, const uint32_t b1) {
    asm volatile("mma.sync.aligned.m16n8k16.row.col.f32.f16.f16.f32 "
                 "{%0,%1,%2,%3}, {%4,%5,%6,%7}, {%8,%9}, {%0,%1,%2,%3};"
                 : "+f"(d[0]), "+f"(d[1]), "+f"(d[2]), "+f"(d[3])
                 : "r"(a[0]), "r"(a[1]), "r"(a[2]), "r"(a[3]),
                   "r"(b0), "r"(b1));
}
__device__ __forceinline__ void cp16(uint32_t dst, const void* src) {
    asm volatile("cp.async.cg.shared.global [%0], [%1], 16;"
                 :: "r"(dst), "l"(src) : "memory");
}
#define CP_COMMIT() asm volatile("cp.async.commit_group;" ::: "memory")
#define CP_WAIT0()  asm volatile("cp.async.wait_group 0;" ::: "memory")

__device__ __forceinline__ uint32_t h2u(float a, float b) {
    __half2 h = __floats2half2_rn(a, b);
    return *reinterpret_cast<uint32_t*>(&h);
}

// ---------------------------------------------------------------------------
// Kernel 1: embedding-bag -> plain fp16. 1 row/warp, 4 rows/block,
// single 9216-block launch (measured-best shape, smooth waves).
// ---------------------------------------------------------------------------
__global__ void embed_kernel(const int* __restrict__ conv,
                             const int* __restrict__ kb,
                             const float* __restrict__ Ctab,
                             const float* __restrict__ Ktab) {
    const int lane = threadIdx.x & 31;
    const int row  = blockIdx.x * 4 + (threadIdx.x >> 5);
    const int NC   = HOPS * BB * LC;

    const int* idx;
    const float* tab;
    __half* dst;
    if (row < NC) {
        const int hop = row / (BB * LC);
        const int rem = row - hop * (BB * LC);
        idx = conv + rem * MC;
        tab = Ctab + (size_t)hop * VV * DD;
        dst = g_cf + (size_t)row * DD;
    } else {
        const int r2  = row - NC;
        const int hop = r2 / (BB * LK);
        const int rem = r2 - hop * (BB * LK);
        idx = kb + rem * MK;
        tab = Ktab + (size_t)hop * VV * DD;
        dst = g_kf + (size_t)r2 * DD;
    }
    float4 s = make_float4(0.f, 0.f, 0.f, 0.f);
    #pragma unroll
    for (int m = 0; m < 8; m++) {
        const float4 v = ((const float4*)(tab + (size_t)idx[m] * DD))[lane];
        s.x += v.x; s.y += v.y; s.z += v.z; s.w += v.w;
    }
    ((__half2*)(dst + 4 * lane))[0] = __floats2half2_rn(s.x, s.y);
    ((__half2*)(dst + 4 * lane))[1] = __floats2half2_rn(s.z, s.w);
}

// ---------------------------------------------------------------------------
// Kernel 2: warp-MMA flash attention, k-split, double-buffered cp.async.
// grid = (LC/TQ, BB, HOPS*KS) = (4,16,6) = 384 blocks, 128 thr,
// __launch_bounds__(128,4): reg cap 128 -> 4 blocks/SM (16 warps).
// A-fragments re-loaded from the resident cf smem plane per use (no 32-reg
// persistent cache), freeing registers for occupancy.
// ---------------------------------------------------------------------------
extern __shared__ __half smem_h[];

__global__ __launch_bounds__(128, 4)
void attn_kernel() {
    const int tid  = threadIdx.x;
    const int lane = tid & 31;
    const int w    = tid >> 5;
    const int g    = lane >> 2;
    const int t4   = lane & 3;
    const int lbase  = blockIdx.x * TQ;
    const int b      = blockIdx.y;
    const int hop    = blockIdx.z >> 1;
    const int ksplit = blockIdx.z & 1;
    const int pair   = hop * BB + b;

    const uint32_t sb = smem_u32(smem_h);
    const uint32_t BUFSZ = TK * KF_PITCH * 2;   // 17408 bytes per plane

    // ---- stage cf into plane 2 (plain stores), issue chunk0 cp.async ----
    {
        const uint4* sh = (const uint4*)(g_cf + ((size_t)pair * LC + lbase) * DD);
        __half* cfp = smem_h + 2 * TK * KF_PITCH;
        for (int i = tid; i < TQ * (DD / 8); i += 128) {
            const int r  = i >> 4;
            const int c8 = i & 15;
            *(uint4*)&cfp[r * KF_PITCH + c8 * 8] = sh[r * (DD / 8) + c8];
        }
        const int ch0 = ksplit * CHUNKS;
        const uint4* kh = (const uint4*)(g_kf + ((size_t)pair * LK + ch0 * TK) * DD);
        for (int i = tid; i < TK * (DD / 8); i += 128) {
            const int r  = i >> 4;
            const int c8 = i & 15;
            cp16(sb + (uint32_t)(r * KF_PITCH + c8 * 8) * 2u, kh + r * (DD / 8) + c8);
        }
        CP_COMMIT();
    }
    __syncthreads();                       // cf visible
    CP_WAIT0();
    __syncthreads();                       // chunk0 ready

    // A-fragment address components (reload from cf plane per use)
    const uint32_t cfpl = sb + 2 * BUFSZ;
    const int asub = lane >> 3;
    const uint32_t a_row_off =
        (uint32_t)(w * 16 + (lane & 7) + ((asub & 1) << 3)) * KF_PITCH;
    const uint32_t a_col0 = (uint32_t)((asub & 2) << 2);

    // x4 lane addressing components
    const int r8   = lane & 7;
    const int gq   = lane >> 3;
    const uint32_t sc_row_off = (uint32_t)(((gq >> 1) << 3) + r8);
    const uint32_t sc_col_off = (uint32_t)((gq & 1) << 3);
    const uint32_t av_row_off = (uint32_t)(((gq & 1) << 3) + r8);
    const uint32_t av_col_off = (uint32_t)((gq >> 1) << 3);

    float out[16][4];
    #pragma unroll
    for (int i = 0; i < 16; i++)
        #pragma unroll
        for (int q = 0; q < 4; q++) out[i][q] = 0.f;
    float sum_r = 0.f, sum_r8 = 0.f;

    for (int c = 0; c < CHUNKS; c++) {
        if (c < CHUNKS - 1) {
            const int chn = ksplit * CHUNKS + c + 1;
            const uint32_t db = sb + (uint32_t)((c + 1) & 1) * BUFSZ;
            const uint4* kh = (const uint4*)(g_kf + ((size_t)pair * LK + chn * TK) * DD);
            for (int i = tid; i < TK * (DD / 8); i += 128) {
                const int r  = i >> 4;
                const int c8 = i & 15;
                cp16(db + (uint32_t)(r * KF_PITCH + c8 * 8) * 2u, kh + r * (DD / 8) + c8);
            }
            CP_COMMIT();
        }

        const uint32_t kf_b = sb + (uint32_t)(c & 1) * BUFSZ;

        // ---- scores + exp; 4 independent acc chains (32 kf rows / pass) ----
        uint32_t pa[4][4];
        #pragma unroll
        for (int p = 0; p < 2; p++) {
            float acc[4][4];
            #pragma unroll
            for (int j = 0; j < 4; j++)
                #pragma unroll
                for (int q = 0; q < 4; q++) acc[j][q] = 0.f;
            const uint32_t rbA = (uint32_t)(p * 32) + sc_row_off;
            const uint32_t rbB = rbA + 16;
            #pragma unroll
            for (int ks = 0; ks < 8; ks++) {
                uint32_t aa[4], bA[4], bB[4];
                ldsm_x4(aa, cfpl + (a_row_off + (uint32_t)(16 * ks) + a_col0) * 2u);
                const uint32_t ko = (uint32_t)(16 * ks) + sc_col_off;
                ldsm_x4(bA, kf_b + (rbA * KF_PITCH + ko) * 2u);
                ldsm_x4(bB, kf_b + (rbB * KF_PITCH + ko) * 2u);
                mma16816(acc[0], aa, bA[0], bA[1]);
                mma16816(acc[1], aa, bA[2], bA[3]);
                mma16816(acc[2], aa, bB[0], bB[1]);
                mma16816(acc[3], aa, bB[2], bB[3]);
            }
            #pragma unroll
            for (int j = 0; j < 4; j++) {
                const int nb = 4 * p + j;
                const float e0 = __expf(acc[j][0]);
                const float e1 = __expf(acc[j][1]);
                const float e2 = __expf(acc[j][2]);
                const float e3 = __expf(acc[j][3]);
                sum_r  += e0 + e1;
                sum_r8 += e2 + e3;
                // D-layout == AV A-layout identity
                pa[nb >> 1][((nb & 1) << 1) + 0] = h2u(e0, e1);
                pa[nb >> 1][((nb & 1) << 1) + 1] = h2u(e2, e3);
            }
        }

        // ---- AV: A = P (regs), B = kf via x4 trans (two dn per load) ----
        #pragma unroll
        for (int dnp = 0; dnp < 8; dnp++) {
            const uint32_t cb = (uint32_t)(dnp * 16) + av_col_off;
            #pragma unroll
            for (int ks = 0; ks < 4; ks++) {
                uint32_t b_h[4];
                const uint32_t off =
                    (((uint32_t)(16 * ks) + av_row_off) * KF_PITCH + cb) * 2u;
                ldsm_x4_t(b_h, kf_b + off);
                mma16816(out[2 * dnp],     pa[ks], b_h[0], b_h[1]);
                mma16816(out[2 * dnp + 1], pa[ks], b_h[2], b_h[3]);
            }
        }

        if (c < CHUNKS - 1) {
            CP_WAIT0();
            __syncthreads();               // next chunk ready; buffer swap safe
        }
    }

    // ---- finalize: quad-reduce row sums, store fp16 partials + fp32 sums ----
    #pragma unroll
    for (int off = 1; off <= 2; off <<= 1) {
        sum_r  += __shfl_xor_sync(0xffffffffu, sum_r,  off);
        sum_r8 += __shfl_xor_sync(0xffffffffu, sum_r8, off);
    }
    const int z = blockIdx.z;
    const int l0 = lbase + w * 16 + g;
    __half* slab = g_part + (size_t)z * LC * BB * DD;
    __half* op0 = slab + ((size_t)l0 * BB + b) * DD;
    __half* op8 = slab + ((size_t)(l0 + 8) * BB + b) * DD;
    if (t4 == 0) {
        g_psum[(size_t)z * LC * BB + (size_t)l0 * BB + b]       = sum_r;
        g_psum[(size_t)z * LC * BB + (size_t)(l0 + 8) * BB + b] = sum_r8;
    }
    #pragma unroll
    for (int dn = 0; dn < 16; dn++) {
        const int col = dn * 8 + 2 * t4;
        *(__half2*)&op0[col] = __floats2half2_rn(out[dn][0], out[dn][1]);
        *(__half2*)&op8[col] = __floats2half2_rn(out[dn][2], out[dn][3]);
    }
}

// ---------------------------------------------------------------------------
// Kernel 3: combine k-split fp16 partials and sum hops -> out [LC, B, D]
// ---------------------------------------------------------------------------
__global__ void reduce_kernel(float* __restrict__ out) {
    const int i = blockIdx.x * blockDim.x + threadIdx.x;     // 4-elem index
    const int rowIdx = i >> 5;                               // (l*BB+b)
    const size_t N4 = (size_t)LC * BB * (DD / 4);
    float4 r = make_float4(0.f, 0.f, 0.f, 0.f);
    #pragma unroll
    for (int hop = 0; hop < HOPS; hop++) {
        const float s = g_psum[(size_t)(hop * KS) * LC * BB + rowIdx] +
                        g_psum[(size_t)(hop * KS + 1) * LC * BB + rowIdx];
        const float inv = 1.f / s;
        float4 acc = make_float4(0.f, 0.f, 0.f, 0.f);
        #pragma unroll
        for (int ks = 0; ks < KS; ks++) {
            const size_t z = (size_t)(hop * KS + ks);
            const __half2* p = (const __half2*)(g_part + (z * N4 + i) * 4);
            const float2 f0 = __half22float2(p[0]);
            const float2 f1 = __half22float2(p[1]);
            acc.x += f0.x; acc.y += f0.y; acc.z += f1.x; acc.w += f1.y;
        }
        r.x += acc.x * inv;
        r.y += acc.y * inv;
        r.z += acc.z * inv;
        r.w += acc.w * inv;
    }
    ((float4*)out)[i] = r;
}

// ---------------------------------------------------------------------------
extern "C" void kernel_launch(void* const* d_in, const int* in_sizes, int n_in,
                              void* d_out, int out_size) {
    const int*   conv = (const int*)d_in[0];
    const int*   kb   = (const int*)d_in[1];
    const float* Ctab = (const float*)d_in[2];
    const float* Ktab = (const float*)d_in[3];
    float* out = (float*)d_out;

    const int smem_bytes = 3 * TK * KF_PITCH * 2;        // 52224
    cudaFuncSetAttribute(attn_kernel,
                         cudaFuncAttributeMaxDynamicSharedMemorySize, smem_bytes);

    const int n_rows = HOPS * BB * (LC + LK);            // 36864
    embed_kernel<<<n_rows / 4, 128>>>(conv, kb, Ctab, Ktab);
    attn_kernel<<<dim3(LC / TQ, BB, HOPS * KS), 128, smem_bytes>>>();
    const int n4 = LC * BB * DD / 4;                     // 131072
    reduce_kernel<<<n4 / 256, 256>>>(out);
}